// round 10
// baseline (speedup 1.0000x reference)
#include <cuda_runtime.h>
#include <math.h>
#include <stdint.h>

#define BATCH 8
#define NSEQ  12306
#define NOUT  192                 // TS^3 * 3
#define PAIRS (BATCH * NOUT)      // 1536

#define BC_BLOCKS 592             // 148 SMs * 4 blocks (exactly one wave)
#define BC_THR    512
#define NQ4 4725504               // 1536*12306/4 float4 in output

// Activation scratch + final MLP outputs
__device__ float g_h1[BATCH * 512];
__device__ float g_h2[BATCH * 1024];
__device__ float g_h3[BATCH * 512];
__device__ float g_o [PAIRS];

// ---------- helpers ----------
__device__ __forceinline__ uint64_t policy_evict_last()
{
    uint64_t pol;
    asm("createpolicy.fractional.L2::evict_last.b64 %0, 1.0;" : "=l"(pol));
    return pol;
}

// Weight load: L2-sticky (evict_last) read-only vector load.
__device__ __forceinline__ float4 ldw(const float4* p, uint64_t pol)
{
    float4 v;
    asm volatile("ld.global.nc.L2::cache_hint.v4.f32 {%0,%1,%2,%3}, [%4], %5;"
                 : "=f"(v.x), "=f"(v.y), "=f"(v.z), "=f"(v.w)
                 : "l"(p), "l"(pol));
    return v;
}

// Streaming store (evict-first): don't let the 75.6MB output sweep L2.
__device__ __forceinline__ void stcs(float4* p, float4 v)
{
    asm volatile("st.global.cs.v4.f32 [%0], {%1,%2,%3,%4};"
                 :: "l"(p), "f"(v.x), "f"(v.y), "f"(v.z), "f"(v.w) : "memory");
}

__device__ __forceinline__ float gelu_exact(float v)
{
    return 0.5f * v * (1.0f + erff(v * 0.70710678118654752440f));
}

// ---------------- Per-layer kernel ----------------
// X: [BATCH, K], W: [N, K] row-major, Y: [BATCH, N].
// Block = 256 thr = 8 warps; warp w computes neuron n = bid*8 + w for ALL 8
// batches (acc[8], activations reused from smem). Grid = N/8.
// ACT: 0 = exact GELU, 1 = sigmoid.
template <int K, int ACT>
__global__ void __launch_bounds__(256, 4)
layer_kernel(const float* __restrict__ X,
             const float* __restrict__ W,
             const float* __restrict__ bias,
             float* __restrict__ Y,
             int N)
{
    __shared__ float4 xs[BATCH * K / 4];

    const uint64_t pol = policy_evict_last();

    // Stage all 8 batch rows (float4).
    const float4* X4 = reinterpret_cast<const float4*>(X);
    for (int i = threadIdx.x; i < BATCH * (K / 4); i += 256) xs[i] = X4[i];
    __syncthreads();

    const int wid  = threadIdx.x >> 5;
    const int lane = threadIdx.x & 31;
    const int n    = blockIdx.x * 8 + wid;

    const float4* wrow = reinterpret_cast<const float4*>(W + (size_t)n * K);

    float acc[BATCH];
#pragma unroll
    for (int b = 0; b < BATCH; b++) acc[b] = 0.0f;

#pragma unroll
    for (int i = lane; i < K / 4; i += 32) {
        float4 w4 = ldw(wrow + i, pol);
#pragma unroll
        for (int b = 0; b < BATCH; b++) {
            float4 x4 = xs[b * (K / 4) + i];
            acc[b] += w4.x * x4.x + w4.y * x4.y + w4.z * x4.z + w4.w * x4.w;
        }
    }

#pragma unroll
    for (int off = 16; off; off >>= 1)
#pragma unroll
        for (int b = 0; b < BATCH; b++)
            acc[b] += __shfl_xor_sync(0xffffffffu, acc[b], off);

    if (lane < BATCH) {
        float v = acc[lane] + bias[n];
        if (ACT == 0)
            v = 0.5f * v * (1.0f + erff(v * 0.70710678118654752440f));
        else
            v = 1.0f / (1.0f + expf(-v));
        Y[(size_t)lane * N + n] = v;
    }
}

// ---------------- Broadcast (unchanged: at the write-path floor) ----------
// out.flat[j] = g_o[j / NSEQ]. NSEQ % 4 == 2: a float4 straddles a pair
// boundary iff r == NSEQ-2.
__global__ void __launch_bounds__(BC_THR, 4)
bcast_kernel(float* __restrict__ out)
{
    float4* o4 = reinterpret_cast<float4*>(out);
    const unsigned stride = BC_BLOCKS * BC_THR;

    for (unsigned q = blockIdx.x * BC_THR + threadIdx.x; q < NQ4; q += stride) {
        const unsigned j = q << 2;
        const unsigned p = j / NSEQ;            // const-divide -> mulhi chain
        const unsigned r = j - p * NSEQ;
        const float a = __ldg(&g_o[p]);
        float4 v;
        if (r == NSEQ - 2) {                    // rare straddle (a,a,b,b)
            const float b = __ldg(&g_o[p + 1]);
            v = make_float4(a, a, b, b);
        } else {
            v = make_float4(a, a, a, a);
        }
        stcs(o4 + q, v);
    }
}

extern "C" void kernel_launch(void* const* d_in, const int* in_sizes, int n_in,
                              void* d_out, int out_size)
{
    const float* x  = (const float*)d_in[0];
    const float* W1 = (const float*)d_in[1];
    const float* b1 = (const float*)d_in[2];
    const float* W2 = (const float*)d_in[3];
    const float* b2 = (const float*)d_in[4];
    const float* W3 = (const float*)d_in[5];
    const float* b3 = (const float*)d_in[6];
    const float* W4 = (const float*)d_in[7];
    const float* b4 = (const float*)d_in[8];

    float *h1, *h2, *h3, *o;
    cudaGetSymbolAddress((void**)&h1, g_h1);
    cudaGetSymbolAddress((void**)&h2, g_h2);
    cudaGetSymbolAddress((void**)&h3, g_h3);
    cudaGetSymbolAddress((void**)&o,  g_o);

    layer_kernel<256,  0><<< 512 / 8, 256>>>(x,  W1, b1, h1, 512);
    layer_kernel<512,  0><<<1024 / 8, 256>>>(h1, W2, b2, h2, 1024);
    layer_kernel<1024, 0><<< 512 / 8, 256>>>(h2, W3, b3, h3, 512);
    layer_kernel<512,  1><<< NOUT / 8, 256>>>(h3, W4, b4, o, NOUT);

    bcast_kernel<<<BC_BLOCKS, BC_THR>>>((float*)d_out);
}

// round 11
// speedup vs baseline: 1.2388x; 1.2388x over previous
#include <cuda_runtime.h>
#include <math.h>
#include <stdint.h>

#define BATCH 8
#define NSEQ  12306
#define NOUT  192                 // TS^3 * 3
#define PAIRS (BATCH * NOUT)      // 1536
#define MLP_THR 1024

#define BC_BLOCKS 592             // 148 SMs * 4 blocks (exactly one wave)
#define BC_THR    512
#define NQ4 4725504               // 1536*12306/4 float4 in output

// Final MLP outputs (read by bcast kernel; kernel boundary orders memory)
__device__ float g_o[PAIRS];

// ---------- helpers ----------
__device__ __forceinline__ uint32_t smem_u32(const void* p)
{
    uint32_t a;
    asm("{ .reg .u64 t; cvta.to.shared.u64 t, %1; cvt.u32.u64 %0, t; }"
        : "=r"(a) : "l"(p));
    return a;
}

__device__ __forceinline__ uint64_t policy_evict_last()
{
    uint64_t pol;
    asm("createpolicy.fractional.L2::evict_last.b64 %0, 1.0;" : "=l"(pol));
    return pol;
}

// Weight load: L2-sticky (evict_last) read-only vector load.
__device__ __forceinline__ float4 ldw(const float4* p, uint64_t pol)
{
    float4 v;
    asm volatile("ld.global.nc.L2::cache_hint.v4.f32 {%0,%1,%2,%3}, [%4], %5;"
                 : "=f"(v.x), "=f"(v.y), "=f"(v.z), "=f"(v.w)
                 : "l"(p), "l"(pol));
    return v;
}

// Streaming store (evict-first): don't let the 75.6MB output sweep L2.
__device__ __forceinline__ void stcs(float4* p, float4 v)
{
    asm volatile("st.global.cs.v4.f32 [%0], {%1,%2,%3,%4};"
                 :: "l"(p), "f"(v.x), "f"(v.y), "f"(v.z), "f"(v.w) : "memory");
}

// Store one float to the smem word of CTA `rank` in this cluster.
__device__ __forceinline__ void dsmem_st32(uint32_t laddr, uint32_t rank, float a)
{
    asm volatile("{ .reg .b32 r; mapa.shared::cluster.u32 r, %0, %1; "
                 "st.shared::cluster.b32 [r], %2; }"
                 :: "r"(laddr), "r"(rank), "f"(a) : "memory");
}

__device__ __forceinline__ void csync()
{
    asm volatile("barrier.cluster.arrive.aligned;" ::: "memory");
    asm volatile("barrier.cluster.wait.aligned;"   ::: "memory");
}

__device__ __forceinline__ float gelu_exact(float v)
{
    return 0.5f * v * (1.0f + erff(v * 0.70710678118654752440f));
}

// NPW neuron dot products of length K against smem row `in`; warp-collective.
template <int K, int NPW>
__device__ __forceinline__ void warp_dotN(const float* __restrict__ in,
                                          const float* __restrict__ W,
                                          int n0, int lane, uint64_t pol,
                                          float* acc)
{
    const float4* in4 = reinterpret_cast<const float4*>(in);
    const float4* wr[NPW];
#pragma unroll
    for (int j = 0; j < NPW; j++) {
        acc[j] = 0.0f;
        wr[j]  = reinterpret_cast<const float4*>(W + (size_t)(n0 + j) * K);
    }
#pragma unroll
    for (int i = lane; i < K / 4; i += 32) {
        float4 x4 = in4[i];
#pragma unroll
        for (int j = 0; j < NPW; j++) {
            float4 w4 = ldw(wr[j] + i, pol);
            acc[j] += w4.x * x4.x + w4.y * x4.y + w4.z * x4.z + w4.w * x4.w;
        }
    }
#pragma unroll
    for (int off = 16; off; off >>= 1)
#pragma unroll
        for (int j = 0; j < NPW; j++)
            acc[j] += __shfl_xor_sync(0xffffffffu, acc[j], off);
}

// ---------------- MLP kernel: one CS-CTA cluster per batch ----------------
// Launched with runtime cluster dim {CS,1,1}; rank = blockIdx.x % CS.
// Activations replicated to all cluster CTAs' smem via DSMEM stores.
template <int CS>
__global__ void __launch_bounds__(MLP_THR, 1)
mlp_kernel(const float* __restrict__ x,
           const float* __restrict__ W1, const float* __restrict__ b1,
           const float* __restrict__ W2, const float* __restrict__ b2,
           const float* __restrict__ W3, const float* __restrict__ b3,
           const float* __restrict__ W4, const float* __restrict__ b4)
{
    __shared__ float A[1024];   // holds x, then h2
    __shared__ float B[1024];   // holds h1, then h3

    constexpr int NPW1 = 512  / (CS * 32);   // CS=8: 2, CS=16: 1
    constexpr int NPW2 = 1024 / (CS * 32);   // 4 / 2
    constexpr int NPW3 = 512  / (CS * 32);   // 2 / 1
    constexpr int OPC  = NOUT / CS;          // 24 / 12

    const int bid   = blockIdx.x;
    const int g     = bid / CS;              // batch 0..7
    const uint32_t rank = bid % CS;          // cluster ctarank (1D contiguous)
    const int wid   = threadIdx.x >> 5;
    const int lane  = threadIdx.x & 31;

    const uint64_t pol = policy_evict_last();
    const uint32_t Aaddr = smem_u32(A);
    const uint32_t Baddr = smem_u32(B);

    // Stage x[g] (256 floats) locally into A.
    if (threadIdx.x < 64)
        reinterpret_cast<float4*>(A)[threadIdx.x] =
            reinterpret_cast<const float4*>(x + (size_t)g * 256)[threadIdx.x];
    __syncthreads();

    // ---- L1: A(256) -> 512, GELU -> B (replicated) ----
    {
        const int n0 = (int)rank * (NPW1 * 32) + wid * NPW1;
        float acc[NPW1];
        warp_dotN<256, NPW1>(A, W1, n0, lane, pol, acc);
        if (lane == 0) {
#pragma unroll
            for (int j = 0; j < NPW1; j++) {
                float v = gelu_exact(acc[j] + b1[n0 + j]);
#pragma unroll
                for (uint32_t r = 0; r < (uint32_t)CS; r++)
                    dsmem_st32(Baddr + (uint32_t)(n0 + j) * 4u, r, v);
            }
        }
    }
    csync();

    // ---- L2: B(512) -> 1024, GELU -> A (replicated; A's x is dead) ----
    {
        const int n0 = (int)rank * (NPW2 * 32) + wid * NPW2;
        float acc[NPW2];
        warp_dotN<512, NPW2>(B, W2, n0, lane, pol, acc);
        if (lane == 0) {
#pragma unroll
            for (int j = 0; j < NPW2; j++) {
                float v = gelu_exact(acc[j] + b2[n0 + j]);
#pragma unroll
                for (uint32_t r = 0; r < (uint32_t)CS; r++)
                    dsmem_st32(Aaddr + (uint32_t)(n0 + j) * 4u, r, v);
            }
        }
    }
    csync();

    // ---- L3: A(1024) -> 512, GELU -> B (replicated; h1 is dead) ----
    {
        const int n0 = (int)rank * (NPW3 * 32) + wid * NPW3;
        float acc[NPW3];
        warp_dotN<1024, NPW3>(A, W3, n0, lane, pol, acc);
        if (lane == 0) {
#pragma unroll
            for (int j = 0; j < NPW3; j++) {
                float v = gelu_exact(acc[j] + b3[n0 + j]);
#pragma unroll
                for (uint32_t r = 0; r < (uint32_t)CS; r++)
                    dsmem_st32(Baddr + (uint32_t)(n0 + j) * 4u, r, v);
            }
        }
    }
    csync();

    // ---- L4: B(512) -> OPC outputs per CTA, sigmoid -> g_o ----
    if (wid < OPC) {
        const int o = (int)rank * OPC + wid;     // 0..191
        float acc[1];
        warp_dotN<512, 1>(B, W4, o, lane, pol, acc);
        if (lane == 0)
            g_o[g * NOUT + o] = 1.0f / (1.0f + expf(-(acc[0] + b4[o])));
    }
}

// ---------------- Broadcast (unchanged: at the write-path floor) ----------
__global__ void __launch_bounds__(BC_THR, 4)
bcast_kernel(float* __restrict__ out)
{
    float4* o4 = reinterpret_cast<float4*>(out);
    const unsigned stride = BC_BLOCKS * BC_THR;

    for (unsigned q = blockIdx.x * BC_THR + threadIdx.x; q < NQ4; q += stride) {
        const unsigned j = q << 2;
        const unsigned p = j / NSEQ;            // const-divide -> mulhi chain
        const unsigned r = j - p * NSEQ;
        const float a = __ldg(&g_o[p]);
        float4 v;
        if (r == NSEQ - 2) {                    // rare straddle (a,a,b,b)
            const float b = __ldg(&g_o[p + 1]);
            v = make_float4(a, a, b, b);
        } else {
            v = make_float4(a, a, a, a);
        }
        stcs(o4 + q, v);
    }
}

extern "C" void kernel_launch(void* const* d_in, const int* in_sizes, int n_in,
                              void* d_out, int out_size)
{
    const float* x  = (const float*)d_in[0];
    const float* W1 = (const float*)d_in[1];
    const float* b1 = (const float*)d_in[2];
    const float* W2 = (const float*)d_in[3];
    const float* b2 = (const float*)d_in[4];
    const float* W3 = (const float*)d_in[5];
    const float* b3 = (const float*)d_in[6];
    const float* W4 = (const float*)d_in[7];
    const float* b4 = (const float*)d_in[8];

    // Try 16-CTA clusters (nonportable); fall back to portable 8-CTA clusters.
    bool did16 = false;
    if (cudaFuncSetAttribute((const void*)mlp_kernel<16>,
                             cudaFuncAttributeNonPortableClusterSizeAllowed, 1)
        == cudaSuccess) {
        cudaLaunchConfig_t cfg = {};
        cfg.gridDim  = dim3(BATCH * 16, 1, 1);
        cfg.blockDim = dim3(MLP_THR, 1, 1);
        cudaLaunchAttribute at[1];
        at[0].id = cudaLaunchAttributeClusterDimension;
        at[0].val.clusterDim.x = 16;
        at[0].val.clusterDim.y = 1;
        at[0].val.clusterDim.z = 1;
        cfg.attrs = at;
        cfg.numAttrs = 1;
        cfg.stream = 0;
        if (cudaLaunchKernelEx(&cfg, mlp_kernel<16>,
                               x, W1, b1, W2, b2, W3, b3, W4, b4)
            == cudaSuccess)
            did16 = true;
    }
    if (!did16) {
        cudaGetLastError();   // clear any failed-launch error
        cudaLaunchConfig_t cfg = {};
        cfg.gridDim  = dim3(BATCH * 8, 1, 1);
        cfg.blockDim = dim3(MLP_THR, 1, 1);
        cudaLaunchAttribute at[1];
        at[0].id = cudaLaunchAttributeClusterDimension;
        at[0].val.clusterDim.x = 8;
        at[0].val.clusterDim.y = 1;
        at[0].val.clusterDim.z = 1;
        cfg.attrs = at;
        cfg.numAttrs = 1;
        cfg.stream = 0;
        cudaLaunchKernelEx(&cfg, mlp_kernel<8>,
                           x, W1, b1, W2, b2, W3, b3, W4, b4);
    }

    bcast_kernel<<<BC_BLOCKS, BC_THR>>>((float*)d_out);
}

// round 12
// speedup vs baseline: 1.3303x; 1.0738x over previous
#include <cuda_runtime.h>
#include <math.h>
#include <stdint.h>

#define BATCH 8
#define NSEQ  12306
#define NOUT  192                 // TS^3 * 3
#define PAIRS (BATCH * NOUT)      // 1536
#define CSIZE 8                   // cluster size = blocks per batch
#define MLP_BLOCKS (BATCH * CSIZE)   // 64
#define MLP_THR 1024

#define BC_BLOCKS 592             // 148 SMs * 4 blocks (exactly one wave)
#define BC_THR    512
#define NQ4 4725504               // 1536*12306/4 float4 in output

// Final MLP outputs (read by bcast kernel)
__device__ float g_o[PAIRS];

// ---------- helpers ----------
__device__ __forceinline__ uint32_t smem_u32(const void* p)
{
    uint32_t a;
    asm("{ .reg .u64 t; cvta.to.shared.u64 t, %1; cvt.u32.u64 %0, t; }"
        : "=r"(a) : "l"(p));
    return a;
}

__device__ __forceinline__ void pf_l2_last(const void* p)
{
    asm volatile("prefetch.global.L2::evict_last [%0];" :: "l"(p));
}

__device__ __forceinline__ void pf_l1(const void* p)
{
    asm volatile("prefetch.global.L1 [%0];" :: "l"(p));
}

// Streaming store (evict-first): don't let the 75.6MB output sweep L2.
__device__ __forceinline__ void stcs(float4* p, float4 v)
{
    asm volatile("st.global.cs.v4.f32 [%0], {%1,%2,%3,%4};"
                 :: "l"(p), "f"(v.x), "f"(v.y), "f"(v.z), "f"(v.w) : "memory");
}

// Store {a,b} to the smem word of CTA `rank` in this cluster.
__device__ __forceinline__ void dsmem_st64(uint32_t laddr, uint32_t rank,
                                           float a, float b)
{
    uint64_t v;
    asm("mov.b64 %0, {%1, %2};" : "=l"(v) : "f"(a), "f"(b));
    asm volatile("{ .reg .b32 r; mapa.shared::cluster.u32 r, %0, %1; "
                 "st.shared::cluster.b64 [r], %2; }"
                 :: "r"(laddr), "r"(rank), "l"(v) : "memory");
}

__device__ __forceinline__ void csync()
{
    asm volatile("barrier.cluster.arrive.aligned;" ::: "memory");
    asm volatile("barrier.cluster.wait.aligned;"   ::: "memory");
}

__device__ __forceinline__ float gelu_exact(float v)
{
    return 0.5f * v * (1.0f + erff(v * 0.70710678118654752440f));
}

// NPW neuron dot products of length K against smem row `in`; warp-collective.
// Plain __ldg weight loads (no cache-hint path).
template <int K, int NPW>
__device__ __forceinline__ void warp_dotN(const float* __restrict__ in,
                                          const float* __restrict__ W,
                                          int n0, int lane, float* acc)
{
    const float4* in4 = reinterpret_cast<const float4*>(in);
    const float4* wr[NPW];
#pragma unroll
    for (int j = 0; j < NPW; j++) {
        acc[j] = 0.0f;
        wr[j]  = reinterpret_cast<const float4*>(W + (size_t)(n0 + j) * K);
    }
#pragma unroll
    for (int i = lane; i < K / 4; i += 32) {
        float4 x4 = in4[i];
#pragma unroll
        for (int j = 0; j < NPW; j++) {
            float4 w4 = __ldg(wr[j] + i);
            acc[j] += w4.x * x4.x + w4.y * x4.y + w4.z * x4.z + w4.w * x4.w;
        }
    }
#pragma unroll
    for (int off = 16; off; off >>= 1)
#pragma unroll
        for (int j = 0; j < NPW; j++)
            acc[j] += __shfl_xor_sync(0xffffffffu, acc[j], off);
}

// ---------------- Kernel 1: MLP (one 8-CTA cluster per batch) ----------------
__global__ void __launch_bounds__(MLP_THR, 1) __cluster_dims__(CSIZE, 1, 1)
mlp_kernel(const float* __restrict__ x,
           const float* __restrict__ W1, const float* __restrict__ b1,
           const float* __restrict__ W2, const float* __restrict__ b2,
           const float* __restrict__ W3, const float* __restrict__ b3,
           const float* __restrict__ W4, const float* __restrict__ b4)
{
    __shared__ float A[1024];   // holds x, then h2
    __shared__ float B[1024];   // holds h1, then h3

    const int bid   = blockIdx.x;
    const int g     = bid / CSIZE;          // batch 0..7
    const uint32_t rank = bid % CSIZE;      // cluster ctarank (1D launch)
    const int wid   = threadIdx.x >> 5;
    const int lane  = threadIdx.x & 31;
    const int tid   = threadIdx.x;

    // L2 residency pin: touch every weight line with evict_last class.
    {
        const int t = bid * MLP_THR + tid;   // 65536 threads >= 39936 lines
        const float* pf = nullptr;
        if      (t < 4096)  pf = W1 + (size_t)t * 32;
        else if (t < 20480) pf = W2 + (size_t)(t - 4096)  * 32;
        else if (t < 36864) pf = W3 + (size_t)(t - 20480) * 32;
        else if (t < 39936) pf = W4 + (size_t)(t - 36864) * 32;
        if (pf) pf_l2_last(pf);
    }

    const uint32_t Aaddr = smem_u32(A);
    const uint32_t Baddr = smem_u32(B);

    // Stage x[g] (256 floats) locally into A.
    if (tid < 64)
        reinterpret_cast<float4*>(A)[tid] =
            reinterpret_cast<const float4*>(x + (size_t)g * 256)[tid];
    __syncthreads();

    // ---- L1: A(256) -> 512, GELU. 2 neurons/warp -> B (replicated) ----
    {
        const int n = (int)rank * 64 + wid * 2;
        float acc[2];
        warp_dotN<256, 2>(A, W1, n, lane, acc);
        if (lane == 0) {
            float v0 = gelu_exact(acc[0] + b1[n]);
            float v1 = gelu_exact(acc[1] + b1[n + 1]);
#pragma unroll
            for (uint32_t r = 0; r < CSIZE; r++)
                dsmem_st64(Baddr + n * 4u, r, v0, v1);
        }
    }
    // Hide next layer's L1 fill under the barrier: W2 slice = 2048 lines.
    {
        const float* base = W2 + (size_t)((int)rank * 128) * 512;
        pf_l1(base + (size_t)(tid * 2)     * 32);
        pf_l1(base + (size_t)(tid * 2 + 1) * 32);
    }
    csync();

    // ---- L2: B(512) -> 1024, GELU. 4 neurons/warp -> A (replicated) ----
    {
        const int n = (int)rank * 128 + wid * 4;
        float acc[4];
        warp_dotN<512, 4>(B, W2, n, lane, acc);
        if (lane == 0) {
            float v0 = gelu_exact(acc[0] + b2[n]);
            float v1 = gelu_exact(acc[1] + b2[n + 1]);
            float v2 = gelu_exact(acc[2] + b2[n + 2]);
            float v3 = gelu_exact(acc[3] + b2[n + 3]);
#pragma unroll
            for (uint32_t r = 0; r < CSIZE; r++) {
                dsmem_st64(Aaddr + n * 4u,     r, v0, v1);
                dsmem_st64(Aaddr + n * 4u + 8, r, v2, v3);
            }
        }
    }
    // W3 slice = 2048 lines.
    {
        const float* base = W3 + (size_t)((int)rank * 64) * 1024;
        pf_l1(base + (size_t)(tid * 2)     * 32);
        pf_l1(base + (size_t)(tid * 2 + 1) * 32);
    }
    csync();

    // ---- L3: A(1024) -> 512, GELU. 2 neurons/warp -> B (replicated) ----
    {
        const int n = (int)rank * 64 + wid * 2;
        float acc[2];
        warp_dotN<1024, 2>(A, W3, n, lane, acc);
        if (lane == 0) {
            float v0 = gelu_exact(acc[0] + b3[n]);
            float v1 = gelu_exact(acc[1] + b3[n + 1]);
#pragma unroll
            for (uint32_t r = 0; r < CSIZE; r++)
                dsmem_st64(Baddr + n * 4u, r, v0, v1);
        }
    }
    // W4 slice = 384 lines.
    {
        const float* base = W4 + (size_t)((int)rank * 24) * 512;
        if (tid < 384) pf_l1(base + (size_t)tid * 32);
    }
    csync();

    // ---- L4: B(512) -> 24 outputs/block, sigmoid -> g_o ----
    if (wid < 24) {
        const int o = (int)rank * 24 + wid;     // 0..191
        float acc[1];
        warp_dotN<512, 1>(B, W4, o, lane, acc);
        if (lane == 0) {
            g_o[g * NOUT + o] = 1.0f / (1.0f + expf(-(acc[0] + b4[o])));
            __threadfence();                    // writer flushes its store
        }
    }
    __syncthreads();
    // PDL: allow the broadcast kernel's blocks to launch now.
    cudaTriggerProgrammaticLaunchCompletion();
}

// ---------------- Kernel 2: broadcast (one wave, streaming stores) ----------
// out.flat[j] = g_o[j / NSEQ]. NSEQ % 4 == 2: a float4 straddles a pair
// boundary iff r == NSEQ-2.
__global__ void __launch_bounds__(BC_THR, 4)
bcast_kernel(float* __restrict__ out)
{
    float4* o4 = reinterpret_cast<float4*>(out);
    const unsigned stride = BC_BLOCKS * BC_THR;
    const unsigned q0 = blockIdx.x * BC_THR + threadIdx.x;

    // Wait for the MLP's g_o writes (no-op when launched without PDL).
    cudaGridDependencySynchronize();

    for (unsigned q = q0; q < NQ4; q += stride) {
        const unsigned j = q << 2;
        const unsigned p = j / NSEQ;            // const-divide -> mulhi chain
        const unsigned r = j - p * NSEQ;
        const float a = __ldg(&g_o[p]);
        float4 v;
        if (r == NSEQ - 2) {                    // rare straddle (a,a,b,b)
            const float b = __ldg(&g_o[p + 1]);
            v = make_float4(a, a, b, b);
        } else {
            v = make_float4(a, a, a, a);
        }
        stcs(o4 + q, v);
    }
}

extern "C" void kernel_launch(void* const* d_in, const int* in_sizes, int n_in,
                              void* d_out, int out_size)
{
    const float* x  = (const float*)d_in[0];
    const float* W1 = (const float*)d_in[1];
    const float* b1 = (const float*)d_in[2];
    const float* W2 = (const float*)d_in[3];
    const float* b2 = (const float*)d_in[4];
    const float* W3 = (const float*)d_in[5];
    const float* b3 = (const float*)d_in[6];
    const float* W4 = (const float*)d_in[7];
    const float* b4 = (const float*)d_in[8];
    float* out = (float*)d_out;

    mlp_kernel<<<MLP_BLOCKS, MLP_THR>>>(x, W1, b1, W2, b2, W3, b3, W4, b4);

    // Broadcast with programmatic dependent launch; fallback to plain launch.
    cudaLaunchConfig_t cfg = {};
    cfg.gridDim  = dim3(BC_BLOCKS, 1, 1);
    cfg.blockDim = dim3(BC_THR, 1, 1);
    cfg.stream   = 0;
    cudaLaunchAttribute at[1];
    at[0].id = cudaLaunchAttributeProgrammaticStreamSerialization;
    at[0].val.programmaticStreamSerializationAllowed = 1;
    cfg.attrs = at;
    cfg.numAttrs = 1;
    if (cudaLaunchKernelEx(&cfg, bcast_kernel, out) != cudaSuccess) {
        cudaGetLastError();                     // clear; plain serialized launch
        bcast_kernel<<<BC_BLOCKS, BC_THR>>>(out);
    }
}

// round 13
// speedup vs baseline: 1.5241x; 1.1457x over previous
#include <cuda_runtime.h>
#include <math.h>
#include <stdint.h>

#define BATCH 8
#define NSEQ  12306
#define NOUT  192                 // TS^3 * 3
#define PAIRS (BATCH * NOUT)      // 1536
#define CSIZE 8                   // cluster size = blocks per batch
#define MLP_BLOCKS (BATCH * CSIZE)   // 64
#define MLP_THR 1024

#define BC_BLOCKS 592             // 148 SMs * 4 blocks (exactly one wave)
#define BC_THR    512
#define NQ4 4725504               // 1536*12306/4 float4 in output

// Final MLP outputs (read by bcast kernel)
__device__ float g_o[PAIRS];

// ---------- helpers ----------
__device__ __forceinline__ uint32_t smem_u32(const void* p)
{
    uint32_t a;
    asm("{ .reg .u64 t; cvta.to.shared.u64 t, %1; cvt.u32.u64 %0, t; }"
        : "=r"(a) : "l"(p));
    return a;
}

__device__ __forceinline__ uint64_t policy_evict_last()
{
    uint64_t pol;
    asm("createpolicy.fractional.L2::evict_last.b64 %0, 1.0;" : "=l"(pol));
    return pol;
}

// Weight load: L2-sticky (evict_last) read-only vector load.  (R9-proven path)
__device__ __forceinline__ float4 ldw(const float4* p, uint64_t pol)
{
    float4 v;
    asm volatile("ld.global.nc.L2::cache_hint.v4.f32 {%0,%1,%2,%3}, [%4], %5;"
                 : "=f"(v.x), "=f"(v.y), "=f"(v.z), "=f"(v.w)
                 : "l"(p), "l"(pol));
    return v;
}

// Streaming store (evict-first): don't let the 75.6MB output sweep L2.
__device__ __forceinline__ void stcs(float4* p, float4 v)
{
    asm volatile("st.global.cs.v4.f32 [%0], {%1,%2,%3,%4};"
                 :: "l"(p), "f"(v.x), "f"(v.y), "f"(v.z), "f"(v.w) : "memory");
}

// Store {a,b} to the smem word of CTA `rank` in this cluster.
__device__ __forceinline__ void dsmem_st64(uint32_t laddr, uint32_t rank,
                                           float a, float b)
{
    uint64_t v;
    asm("mov.b64 %0, {%1, %2};" : "=l"(v) : "f"(a), "f"(b));
    asm volatile("{ .reg .b32 r; mapa.shared::cluster.u32 r, %0, %1; "
                 "st.shared::cluster.b64 [r], %2; }"
                 :: "r"(laddr), "r"(rank), "l"(v) : "memory");
}

__device__ __forceinline__ void csync()
{
    asm volatile("barrier.cluster.arrive.aligned;" ::: "memory");
    asm volatile("barrier.cluster.wait.aligned;"   ::: "memory");
}

__device__ __forceinline__ float gelu_exact(float v)
{
    return 0.5f * v * (1.0f + erff(v * 0.70710678118654752440f));
}

// NPW neuron dot products of length K against smem row `in`; warp-collective.
template <int K, int NPW>
__device__ __forceinline__ void warp_dotN(const float* __restrict__ in,
                                          const float* __restrict__ W,
                                          int n0, int lane, uint64_t pol,
                                          float* acc)
{
    const float4* in4 = reinterpret_cast<const float4*>(in);
    const float4* wr[NPW];
#pragma unroll
    for (int j = 0; j < NPW; j++) {
        acc[j] = 0.0f;
        wr[j]  = reinterpret_cast<const float4*>(W + (size_t)(n0 + j) * K);
    }
#pragma unroll
    for (int i = lane; i < K / 4; i += 32) {
        float4 x4 = in4[i];
#pragma unroll
        for (int j = 0; j < NPW; j++) {
            float4 w4 = ldw(wr[j] + i, pol);
            acc[j] += w4.x * x4.x + w4.y * x4.y + w4.z * x4.z + w4.w * x4.w;
        }
    }
#pragma unroll
    for (int off = 16; off; off >>= 1)
#pragma unroll
        for (int j = 0; j < NPW; j++)
            acc[j] += __shfl_xor_sync(0xffffffffu, acc[j], off);
}

// ---------------- Kernel 1: MLP (one 8-CTA cluster per batch; R9-identical
// except the PDL trigger at the end) ----------------
__global__ void __launch_bounds__(MLP_THR, 1) __cluster_dims__(CSIZE, 1, 1)
mlp_kernel(const float* __restrict__ x,
           const float* __restrict__ W1, const float* __restrict__ b1,
           const float* __restrict__ W2, const float* __restrict__ b2,
           const float* __restrict__ W3, const float* __restrict__ b3,
           const float* __restrict__ W4, const float* __restrict__ b4)
{
    __shared__ float A[1024];   // holds x, then h2
    __shared__ float B[1024];   // holds h1, then h3

    const int bid   = blockIdx.x;
    const int g     = bid / CSIZE;          // batch 0..7
    const uint32_t rank = bid % CSIZE;      // cluster ctarank (1D launch)
    const int wid   = threadIdx.x >> 5;
    const int lane  = threadIdx.x & 31;

    const uint64_t pol = policy_evict_last();
    const uint32_t Aaddr = smem_u32(A);
    const uint32_t Baddr = smem_u32(B);

    // Stage x[g] (256 floats) locally into A.
    if (threadIdx.x < 64)
        reinterpret_cast<float4*>(A)[threadIdx.x] =
            reinterpret_cast<const float4*>(x + (size_t)g * 256)[threadIdx.x];
    __syncthreads();

    // ---- L1: A(256) -> 512, GELU. 2 neurons/warp -> B (replicated) ----
    {
        const int n = (int)rank * 64 + wid * 2;
        float acc[2];
        warp_dotN<256, 2>(A, W1, n, lane, pol, acc);
        if (lane == 0) {
            float v0 = gelu_exact(acc[0] + b1[n]);
            float v1 = gelu_exact(acc[1] + b1[n + 1]);
#pragma unroll
            for (uint32_t r = 0; r < CSIZE; r++)
                dsmem_st64(Baddr + n * 4u, r, v0, v1);
        }
    }
    csync();

    // ---- L2: B(512) -> 1024, GELU. 4 neurons/warp -> A (replicated) ----
    {
        const int n = (int)rank * 128 + wid * 4;
        float acc[4];
        warp_dotN<512, 4>(B, W2, n, lane, pol, acc);
        if (lane == 0) {
            float v0 = gelu_exact(acc[0] + b2[n]);
            float v1 = gelu_exact(acc[1] + b2[n + 1]);
            float v2 = gelu_exact(acc[2] + b2[n + 2]);
            float v3 = gelu_exact(acc[3] + b2[n + 3]);
#pragma unroll
            for (uint32_t r = 0; r < CSIZE; r++) {
                dsmem_st64(Aaddr + n * 4u,     r, v0, v1);
                dsmem_st64(Aaddr + n * 4u + 8, r, v2, v3);
            }
        }
    }
    csync();

    // ---- L3: A(1024) -> 512, GELU. 2 neurons/warp -> B (replicated) ----
    {
        const int n = (int)rank * 64 + wid * 2;
        float acc[2];
        warp_dotN<1024, 2>(A, W3, n, lane, pol, acc);
        if (lane == 0) {
            float v0 = gelu_exact(acc[0] + b3[n]);
            float v1 = gelu_exact(acc[1] + b3[n + 1]);
#pragma unroll
            for (uint32_t r = 0; r < CSIZE; r++)
                dsmem_st64(Baddr + n * 4u, r, v0, v1);
        }
    }
    csync();

    // ---- L4: B(512) -> 24 outputs/block, sigmoid -> g_o ----
    if (wid < 24) {
        const int o = (int)rank * 24 + wid;     // 0..191
        float acc[1];
        warp_dotN<512, 1>(B, W4, o, lane, pol, acc);
        if (lane == 0) {
            g_o[g * NOUT + o] = 1.0f / (1.0f + expf(-(acc[0] + b4[o])));
            __threadfence();                    // publish before PDL trigger
        }
    }
    __syncthreads();
    // PDL: dependent broadcast kernel may begin its g_o reads.
    cudaTriggerProgrammaticLaunchCompletion();
}

// ---------------- Kernel 2: broadcast (one wave, streaming stores) ----------
// out.flat[j] = g_o[j / NSEQ]. NSEQ % 4 == 2: a float4 straddles a pair
// boundary iff r == NSEQ-2.
__global__ void __launch_bounds__(BC_THR, 4)
bcast_kernel(float* __restrict__ out)
{
    float4* o4 = reinterpret_cast<float4*>(out);
    const unsigned stride = BC_BLOCKS * BC_THR;
    const unsigned q0 = blockIdx.x * BC_THR + threadIdx.x;

    // Wait for producer's fenced g_o writes (no-op without PDL).
    cudaGridDependencySynchronize();

    for (unsigned q = q0; q < NQ4; q += stride) {
        const unsigned j = q << 2;
        const unsigned p = j / NSEQ;            // const-divide -> mulhi chain
        const unsigned r = j - p * NSEQ;
        const float a = __ldg(&g_o[p]);
        float4 v;
        if (r == NSEQ - 2) {                    // rare straddle (a,a,b,b)
            const float b = __ldg(&g_o[p + 1]);
            v = make_float4(a, a, b, b);
        } else {
            v = make_float4(a, a, a, a);
        }
        stcs(o4 + q, v);
    }
}

extern "C" void kernel_launch(void* const* d_in, const int* in_sizes, int n_in,
                              void* d_out, int out_size)
{
    const float* x  = (const float*)d_in[0];
    const float* W1 = (const float*)d_in[1];
    const float* b1 = (const float*)d_in[2];
    const float* W2 = (const float*)d_in[3];
    const float* b2 = (const float*)d_in[4];
    const float* W3 = (const float*)d_in[5];
    const float* b3 = (const float*)d_in[6];
    const float* W4 = (const float*)d_in[7];
    const float* b4 = (const float*)d_in[8];
    float* out = (float*)d_out;

    mlp_kernel<<<MLP_BLOCKS, MLP_THR>>>(x, W1, b1, W2, b2, W3, b3, W4, b4);

    // Broadcast with programmatic dependent launch; fallback to plain launch.
    cudaLaunchConfig_t cfg = {};
    cfg.gridDim  = dim3(BC_BLOCKS, 1, 1);
    cfg.blockDim = dim3(BC_THR, 1, 1);
    cfg.stream   = 0;
    cudaLaunchAttribute at[1];
    at[0].id = cudaLaunchAttributeProgrammaticStreamSerialization;
    at[0].val.programmaticStreamSerializationAllowed = 1;
    cfg.attrs = at;
    cfg.numAttrs = 1;
    if (cudaLaunchKernelEx(&cfg, bcast_kernel, out) != cudaSuccess) {
        cudaGetLastError();                     // clear; plain serialized launch
        bcast_kernel<<<BC_BLOCKS, BC_THR>>>(out);
    }
}